// round 7
// baseline (speedup 1.0000x reference)
#include <cuda_runtime.h>

#define CCH 256
#define HH 64
#define WW 64
#define NPIX (HH * WW)

// 4 * 4096 * 256 floats = 16 MB channels-last scratch
__device__ float g_feat_nhwc[4 * NPIX * CCH];

// NCHW -> NHWC transpose: per batch, [C=256][P=4096] -> [P][C]
__global__ __launch_bounds__(256) void transpose_kernel(const float* __restrict__ feat)
{
    __shared__ float tile[32][33];
    const int b  = blockIdx.z;
    const int p0 = blockIdx.x * 32;
    const int c0 = blockIdx.y * 32;
    const int tx = threadIdx.x;
    const int ty = threadIdx.y;
    const float* src = feat + (size_t)b * CCH * NPIX;
    float* dst = g_feat_nhwc + (size_t)b * NPIX * CCH;
#pragma unroll
    for (int i = 0; i < 32; i += 8)
        tile[ty + i][tx] = src[(size_t)(c0 + ty + i) * NPIX + (p0 + tx)];
    __syncthreads();
#pragma unroll
    for (int i = 0; i < 32; i += 8)
        dst[(size_t)(p0 + ty + i) * CCH + (c0 + tx)] = tile[tx][ty + i];
}

// Block = 128 threads (4 warps), 8 blocks/SM. Each block: one ROI, 128
// channels (warp = 32 consecutive channels, lane = channel -> every gather
// is one 128B wavefront). Geometry packed to ONE float4 per bin:
//   { bits: o00 | dx<<20 | dy<<21,  hy*vf,  ly*vf,  lx }
__global__ __launch_bounds__(128, 8) void roialign_maxpool_kernel(
    const float* __restrict__ rois,
    float* __restrict__ out)
{
    __shared__ float4 s_geo[64];
    __shared__ int    s_b;
    __shared__ float4 s_pool4[4][392];   // [warp][ch*49/4] == output order

    const int roi  = blockIdx.x >> 1;
    const int half = blockIdx.x & 1;
    const int tid  = threadIdx.x;

    // ---- per-ROI geometry, one bin per thread 0..63 ----
    if (tid < 64) {
        const float* r = rois + (size_t)roi * 5;
        const float x1 = r[1] * 0.0625f;
        const float y1 = r[2] * 0.0625f;
        const float x2 = r[3] * 0.0625f;
        const float y2 = r[4] * 0.0625f;
        const float bh = (y2 - y1) / 7.0f;
        const float bw = (x2 - x1) / 7.0f;
        const int j = tid >> 3;
        const int i = tid & 7;
        const float ys = y1 + bh * (float)j;
        const float xs = x1 + bw * (float)i;
        const bool valid = (ys >= 0.0f) && (ys < (float)HH) &&
                           (xs >= 0.0f) && (xs < (float)WW);
        const float y0 = floorf(ys);
        const float x0 = floorf(xs);
        const float ly = ys - y0;
        const float lx = xs - x0;
        int iy0 = min(max((int)y0, 0), HH - 1);
        int ix0 = min(max((int)x0, 0), WW - 1);
        const int dy = (iy0 + 1 <= HH - 1) ? 1 : 0;
        const int dx = (ix0 + 1 <= WW - 1) ? 1 : 0;
        const float vf = valid ? 1.0f : 0.0f;
        const int o00 = (iy0 * WW + ix0) * CCH;        // < 2^20
        const int packed = o00 | (dx << 20) | (dy << 21);
        float4 g;
        g.x = __int_as_float(packed);
        g.y = (1.0f - ly) * vf;   // hy * vf
        g.z = ly * vf;            // ly * vf
        g.w = lx;
        s_geo[tid] = g;
        if (tid == 0) s_b = (int)r[0];
    }
    __syncthreads();

    const int warp = tid >> 5;
    const int lane = tid & 31;
    const float* p = g_feat_nhwc + (size_t)s_b * (NPIX * CCH)
                   + half * 128 + warp * 32 + lane;
    float* pool = (float*)&s_pool4[warp][0];

    float prev[8], cur[8];
#pragma unroll
    for (int j = 0; j < 8; j++) {
#pragma unroll
        for (int i = 0; i < 8; i++) {
            const float4 g = s_geo[j * 8 + i];       // ONE LDS.128 broadcast
            const int packed = __float_as_int(g.x);
            const int o00 = packed & 0xFFFFF;
            const int ddx = ((packed >> 20) & 1) * CCH;         // +1 col
            const int ddy = ((packed >> 21) & 1) * (WW * CCH);  // +1 row
            const float hy = g.y;
            const float ly = g.z;
            const float lx = g.w;
            const float hx = 1.0f - lx;
            const float v00 = __ldg(p + o00);
            const float v01 = __ldg(p + o00 + ddx);
            const float v10 = __ldg(p + o00 + ddy);
            const float v11 = __ldg(p + o00 + ddy + ddx);
            cur[i] = hy * (hx * v00 + lx * v01) + ly * (hx * v10 + lx * v11);
        }
        if (j > 0) {
#pragma unroll
            for (int pw = 0; pw < 7; pw++) {
                const float m = fmaxf(fmaxf(prev[pw], prev[pw + 1]),
                                      fmaxf(cur[pw],  cur[pw + 1]));
                pool[lane * 49 + (j - 1) * 7 + pw] = m;   // stride 49: conflict-free
            }
        }
#pragma unroll
        for (int i = 0; i < 8; i++) prev[i] = cur[i];
    }
    __syncwarp();

    // ---- coalesced float4 flush: 392 float4 per warp (12 full + 8-lane tail) ----
    float4* obase = (float4*)(out + ((size_t)roi * CCH + half * 128 + warp * 32) * 49);
    const float4* pp = &s_pool4[warp][0];
#pragma unroll
    for (int it = 0; it < 12; it++)
        obase[it * 32 + lane] = pp[it * 32 + lane];
    if (lane < 8)
        obase[384 + lane] = pp[384 + lane];
}

extern "C" void kernel_launch(void* const* d_in, const int* in_sizes, int n_in,
                              void* d_out, int out_size)
{
    const float* feat = (const float*)d_in[0];  // [4,256,64,64] f32
    const float* rois = (const float*)d_in[1];  // [N,5] f32
    float* out = (float*)d_out;                 // [N,256,7,7] f32
    const int N = in_sizes[1] / 5;

    dim3 tb(32, 8);
    dim3 tg(NPIX / 32, CCH / 32, 4);
    transpose_kernel<<<tg, tb>>>(feat);

    roialign_maxpool_kernel<<<N * 2, 128>>>(rois, out);
}

// round 12
// speedup vs baseline: 1.2658x; 1.2658x over previous
#include <cuda_runtime.h>
#include <cuda_fp16.h>

#define CCH 256
#define HH 64
#define WW 64
#define NPIX (HH * WW)

// fp16 channels-last scratch, channel-interleaved within 64-ch groups:
// half2 slot (pixel, g, c') holds channels (g*64 + c', g*64 + 32 + c').
// 4 batches * 4096 pixels * 128 half2 = 8 MB.
__device__ __half2 g_feat_h[4 * NPIX * (CCH / 2)];

// NCHW fp32 -> interleaved NHWC fp16.
// Block: 32x8. Each block: one batch b, one 64-channel group g, 32 pixels.
__global__ __launch_bounds__(256) void transpose_kernel(const float* __restrict__ feat)
{
    __shared__ float t_lo[32][33];
    __shared__ float t_hi[32][33];
    const int b  = blockIdx.z;
    const int g  = blockIdx.y;            // 64-channel group
    const int p0 = blockIdx.x * 32;
    const int tx = threadIdx.x;
    const int ty = threadIdx.y;
    const float* src = feat + (size_t)b * CCH * NPIX;
#pragma unroll
    for (int i = 0; i < 32; i += 8) {
        t_lo[ty + i][tx] = src[(size_t)(g * 64 +      ty + i) * NPIX + (p0 + tx)];
        t_hi[ty + i][tx] = src[(size_t)(g * 64 + 32 + ty + i) * NPIX + (p0 + tx)];
    }
    __syncthreads();
    __half2* dst = g_feat_h + (size_t)b * (NPIX * (CCH / 2));
#pragma unroll
    for (int i = 0; i < 32; i += 8) {
        const int p = p0 + ty + i;
        // lane tx = local channel c'; half2 = (ch g*64+c', ch g*64+32+c')
        dst[(size_t)p * (CCH / 2) + g * 32 + tx] =
            __floats2half2_rn(t_lo[tx][ty + i], t_hi[tx][ty + i]);
    }
}

// Block = 64 threads (2 warps). Each block: one ROI, 128 channels.
// Warp = one 64-channel group; lane = half2 = channels (c', c'+32).
// Every gather: one LDG.32 of half2 -> 128B warp line in scratch.
__global__ __launch_bounds__(64) void roialign_maxpool_kernel(
    const float* __restrict__ rois,
    float* __restrict__ out)
{
    __shared__ int4   s_off[64];
    __shared__ float4 s_w[64];
    __shared__ int    s_b;
    __shared__ __align__(16) float s_pool[2][64 * 49];  // [warp][64ch][49] == output order

    const int roi  = blockIdx.x >> 1;
    const int half = blockIdx.x & 1;
    const int tid  = threadIdx.x;

    // ---- per-ROI geometry, one bin per thread (valid folded into weights) ----
    {
        const float* r = rois + (size_t)roi * 5;
        const float x1 = r[1] * 0.0625f;
        const float y1 = r[2] * 0.0625f;
        const float x2 = r[3] * 0.0625f;
        const float y2 = r[4] * 0.0625f;
        const float bh = (y2 - y1) / 7.0f;
        const float bw = (x2 - x1) / 7.0f;
        const int j = tid >> 3;
        const int i = tid & 7;
        const float ys = y1 + bh * (float)j;
        const float xs = x1 + bw * (float)i;
        const bool valid = (ys >= 0.0f) && (ys < (float)HH) &&
                           (xs >= 0.0f) && (xs < (float)WW);
        const float y0 = floorf(ys);
        const float x0 = floorf(xs);
        const float ly = ys - y0;
        const float lx = xs - x0;
        int iy0 = min(max((int)y0, 0), HH - 1);
        int ix0 = min(max((int)x0, 0), WW - 1);
        int iy1 = min(iy0 + 1, HH - 1);
        int ix1 = min(ix0 + 1, WW - 1);
        float hy = 1.0f - ly, hx = 1.0f - lx;
        float w00 = hy * hx, w01 = hy * lx, w10 = ly * hx, w11 = ly * lx;
        if (!valid) { w00 = 0.0f; w01 = 0.0f; w10 = 0.0f; w11 = 0.0f; }
        // offsets in half2 units: pixel * 128
        s_off[tid] = make_int4((iy0 * WW + ix0) * (CCH / 2), (iy0 * WW + ix1) * (CCH / 2),
                               (iy1 * WW + ix0) * (CCH / 2), (iy1 * WW + ix1) * (CCH / 2));
        s_w[tid] = make_float4(w00, w01, w10, w11);
        if (tid == 0) s_b = (int)rois[(size_t)roi * 5];
    }
    __syncthreads();

    const int warp = tid >> 5;
    const int lane = tid & 31;
    const int g    = half * 2 + warp;     // 64-channel group index
    const __half2* p = g_feat_h + (size_t)s_b * (NPIX * (CCH / 2)) + g * 32 + lane;
    float* pool = &s_pool[warp][0];

    float2 prev[8], cur[8];
#pragma unroll
    for (int j = 0; j < 8; j++) {
#pragma unroll
        for (int i = 0; i < 8; i++) {
            const int bin = j * 8 + i;
            const int4   o = s_off[bin];   // LDS.128 broadcast
            const float4 w = s_w[bin];     // LDS.128 broadcast
            const float2 f00 = __half22float2(__ldg(p + o.x));
            const float2 f01 = __half22float2(__ldg(p + o.y));
            const float2 f10 = __half22float2(__ldg(p + o.z));
            const float2 f11 = __half22float2(__ldg(p + o.w));
            cur[i].x = w.x * f00.x + w.y * f01.x + w.z * f10.x + w.w * f11.x;
            cur[i].y = w.x * f00.y + w.y * f01.y + w.z * f10.y + w.w * f11.y;
        }
        if (j > 0) {
#pragma unroll
            for (int pw = 0; pw < 7; pw++) {
                const float mx = fmaxf(fmaxf(prev[pw].x, prev[pw + 1].x),
                                       fmaxf(cur[pw].x,  cur[pw + 1].x));
                const float my = fmaxf(fmaxf(prev[pw].y, prev[pw + 1].y),
                                       fmaxf(cur[pw].y,  cur[pw + 1].y));
                const int pos = (j - 1) * 7 + pw;
                // ch = lane: bank 17*lane+pos (bijective); ch = lane+32: +16 (bijective)
                pool[lane * 49 + pos]        = mx;
                pool[(lane + 32) * 49 + pos] = my;
            }
        }
#pragma unroll
        for (int i = 0; i < 8; i++) prev[i] = cur[i];
    }
    __syncwarp();

    // ---- coalesced float4 flush: 64ch * 49 = 784 float4 per warp ----
    float4* obase = (float4*)(out + ((size_t)roi * CCH + g * 64) * 49);
    const float4* pp = (const float4*)pool;
#pragma unroll
    for (int it = 0; it < 24; it++)
        obase[it * 32 + lane] = pp[it * 32 + lane];
    if (lane < 16)
        obase[768 + lane] = pp[768 + lane];
}

extern "C" void kernel_launch(void* const* d_in, const int* in_sizes, int n_in,
                              void* d_out, int out_size)
{
    const float* feat = (const float*)d_in[0];  // [4,256,64,64] f32
    const float* rois = (const float*)d_in[1];  // [N,5] f32
    float* out = (float*)d_out;                 // [N,256,7,7] f32
    const int N = in_sizes[1] / 5;

    dim3 tb(32, 8);
    dim3 tg(NPIX / 32, CCH / 64, 4);
    transpose_kernel<<<tg, tb>>>(feat);

    roialign_maxpool_kernel<<<N * 2, 64>>>(rois, out);
}